// round 13
// baseline (speedup 1.0000x reference)
#include <cuda_runtime.h>
#include <cuda_fp16.h>
#include <stdint.h>

// ---------------- problem constants ----------------
#define NUM_EXEC   50
#define MAXB       60000
#define MAXT       (MAXB * NUM_EXEC)

typedef unsigned long long ull;

// ---------------- device scratch ----------------
__device__ int   g_nsel[MAXB];
__device__ int   g_blocksum[512];
__device__ int   g_rowjob[MAXT];
__device__ float g_base1[(size_t)MAXB * 64];
// prepped weight blob (exact smem image), FRAGMENT-ORDERED B, pure fp16:
//  [0,8192)      W2 frags: kt(4) x nt(8) x lane(32): uint2 {b0,b1}
//  [8192,12288)  W3 frags: kt(4) x nt(4) x lane(32): uint2
//  [12288,13312) fp32 smalls: W1L[64] b2[64] b3[32] W4[32] b4[1]
__device__ __align__(16) unsigned char g_wblob[13312];

// ---------------- helpers ----------------
__device__ __forceinline__ ull fma2(ull a, ull b, ull c) {
    ull d;
    asm("fma.rn.f32x2 %0, %1, %2, %3;" : "=l"(d) : "l"(a), "l"(b), "l"(c));
    return d;
}
__device__ __forceinline__ ull pack2(float a, float b) {
    ull r;
    asm("mov.b64 %0, {%1,%2};" : "=l"(r) : "f"(a), "f"(b));
    return r;
}
__device__ __forceinline__ void unpack2(ull v, float& a, float& b) {
    asm("mov.b64 {%0,%1}, %2;" : "=f"(a), "=f"(b) : "l"(v));
}
__device__ __forceinline__ uint32_t smem_u32(const void* p) {
    uint32_t a;
    asm("{ .reg .u64 t; cvta.to.shared.u64 t, %1; cvt.u32.u64 %0, t; }" : "=r"(a) : "l"(p));
    return a;
}
// pack (lo_elem, hi_elem) -> f16x2, lo_elem in low 16 bits
__device__ __forceinline__ uint32_t packh2(float lov, float hiv) {
    uint32_t r;
    asm("cvt.rn.f16x2.f32 %0, %1, %2;" : "=r"(r) : "f"(hiv), "f"(lov));
    return r;
}
__device__ __forceinline__ void ldmatrix4(uint32_t& a0, uint32_t& a1, uint32_t& a2,
                                          uint32_t& a3, uint32_t addr) {
    asm volatile("ldmatrix.sync.aligned.m8n8.x4.shared.b16 {%0,%1,%2,%3}, [%4];"
                 : "=r"(a0), "=r"(a1), "=r"(a2), "=r"(a3) : "r"(addr));
}
__device__ __forceinline__ void mma16816(float& d0, float& d1, float& d2, float& d3,
                                         uint32_t a0, uint32_t a1, uint32_t a2, uint32_t a3,
                                         uint32_t b0, uint32_t b1) {
    asm volatile("mma.sync.aligned.m16n8k16.row.col.f32.f16.f16.f32 "
                 "{%0,%1,%2,%3}, {%4,%5,%6,%7}, {%8,%9}, {%0,%1,%2,%3};"
                 : "+f"(d0), "+f"(d1), "+f"(d2), "+f"(d3)
                 : "r"(a0), "r"(a1), "r"(a2), "r"(a3), "r"(b0), "r"(b1));
}
// XOR-16B swizzle for 128B rows (A tile only)
__device__ __host__ __forceinline__ uint32_t sw128(uint32_t b) {
    return b ^ ((b >> 3) & 0x70);
}

// ================= prologue 1: nsel gather + block sums, FUSED with weight prep ======
// blocks [0, nb): p1 scan prep; blocks [nb, nb+7): fragment-ordered fp16 weight prep
__global__ void k_p1(const int* __restrict__ job_indices,
                     const int* __restrict__ num_exec_acts, int J,
                     const float* __restrict__ W1, const float* __restrict__ W2,
                     const float* __restrict__ b2, const float* __restrict__ W3,
                     const float* __restrict__ b3, const float* __restrict__ W4,
                     const float* __restrict__ b4) {
    int nb = (J + 255) >> 8;
    if ((int)blockIdx.x < nb) {
        __shared__ int s[256];
        int j = blockIdx.x * 256 + threadIdx.x;
        int v = 0;
        if (j < J) { v = num_exec_acts[job_indices[j]]; g_nsel[j] = v; }
        s[threadIdx.x] = v;
        __syncthreads();
        #pragma unroll
        for (int o = 128; o > 0; o >>= 1) {
            if (threadIdx.x < o) s[threadIdx.x] += s[threadIdx.x + o];
            __syncthreads();
        }
        if (threadIdx.x == 0) g_blocksum[blockIdx.x] = s[0];
    } else {
        int tid = (blockIdx.x - nb) * 256 + threadIdx.x;
        if (tid < 1024) {                 // W2 fragments: kt(4) x nt(8) x lane(32)
            int kt = tid >> 8, nt = (tid >> 5) & 7, lane = tid & 31;
            int q = lane & 3, qr = lane >> 2;
            int n = nt * 8 + qr;
            int k0 = kt * 16 + 2 * q;
            uint2 v;
            v.x = packh2(W2[(k0    ) * 64 + n], W2[(k0 + 1) * 64 + n]);
            v.y = packh2(W2[(k0 + 8) * 64 + n], W2[(k0 + 9) * 64 + n]);
            ((uint2*)g_wblob)[tid] = v;
        } else if (tid < 1536) {          // W3 fragments: kt(4) x nt(4) x lane(32)
            int e = tid - 1024;
            int kt = e >> 7, nt = (e >> 5) & 3, lane = e & 31;
            int q = lane & 3, qr = lane >> 2;
            int n = nt * 8 + qr;
            int k0 = kt * 16 + 2 * q;
            uint2 v;
            v.x = packh2(W3[(k0    ) * 32 + n], W3[(k0 + 1) * 32 + n]);
            v.y = packh2(W3[(k0 + 8) * 32 + n], W3[(k0 + 9) * 32 + n]);
            ((uint2*)g_wblob)[1024 + e] = v;
        } else if (tid < 1536 + 256) {
            int i = tid - 1536;
            float* s = (float*)(g_wblob + 12288);
            if (i < 64)       s[i] = W1[35 * 64 + i];
            else if (i < 128) s[i] = b2[i - 64];
            else if (i < 160) s[i] = b3[i - 128];
            else if (i < 192) s[i] = W4[i - 160];
            else if (i == 192) s[192] = b4[0];
        }
    }
}

// ================= prologue 2: exclusive scan of block sums =================
__global__ void k_scan(int nblocks) {
    __shared__ int s[512];
    int tid = threadIdx.x;
    int v = (tid < nblocks) ? g_blocksum[tid] : 0;
    s[tid] = v;
    __syncthreads();
    for (int o = 1; o < 512; o <<= 1) {
        int t = (tid >= o) ? s[tid - o] : 0;
        __syncthreads();
        s[tid] += t;
        __syncthreads();
    }
    if (tid < nblocks) g_blocksum[tid] = s[tid] - v;
}

// ================= prologue 3: per-job start + row->job fill =================
__global__ void k_p3(int J) {
    __shared__ int s[256];
    int tid = threadIdx.x;
    int j = blockIdx.x * 256 + tid;
    int v = (j < J) ? g_nsel[j] : 0;
    s[tid] = v;
    __syncthreads();
    for (int o = 1; o < 256; o <<= 1) {
        int t = (tid >= o) ? s[tid - o] : 0;
        __syncthreads();
        s[tid] += t;
        __syncthreads();
    }
    if (j < J) {
        int start = (s[tid] - v) + g_blocksum[blockIdx.x];
        for (int k = 0; k < v; k++) g_rowjob[start + k] = j;
    }
}

// ================= prologue 4: base1 v3 — W1 held in registers ==========
// Lane l owns output columns (2l, 2l+1): wreg[i] = W1[i][2l..2l+1]. No smem.
// 64 jobs/block (8 warps x 8 jobs), 4 independent fma2 chains per job.
__global__ void __launch_bounds__(256, 2) k_base1(
    const float* __restrict__ x, const float* __restrict__ h_dag,
    const float* __restrict__ h_glob,
    const int* __restrict__ ptr, const int* __restrict__ jidx,
    const float* __restrict__ W1, const float* __restrict__ b1, int J) {

    const int warp = threadIdx.x >> 5;
    const int lane = threadIdx.x & 31;

    ull wreg[35];
    #pragma unroll
    for (int i = 0; i < 35; i++)
        wreg[i] = *(const ull*)&W1[i * 64 + 2 * lane];
    const ull bias = *(const ull*)&b1[2 * lane];

    const int jbase = blockIdx.x * 64 + warp;

    #pragma unroll 1
    for (int it = 0; it < 8; it++) {
        int j = jbase + it * 8;
        if (j >= J) break;

        int ji = jidx[j];
        const float*  xr = x + (long long)ptr[ji] * 5;
        const float4* hd = (const float4*)(h_dag + (long long)ji * 16);
        const float4* hg = (const float4*)(h_glob + (long long)j * 16);

        // batch all input loads (11 LDG, broadcast across lanes)
        float x0 = xr[0], x1 = xr[1], x2 = xr[2];
        float4 d0 = hd[0], d1 = hd[1], d2 = hd[2], d3 = hd[3];
        float4 g0 = hg[0], g1 = hg[1], g2 = hg[2], g3 = hg[3];

        ull aA = bias, aB = pack2(0.0f, 0.0f), aC = pack2(0.0f, 0.0f), aD = pack2(0.0f, 0.0f);

        aA = fma2(pack2(x0, x0), wreg[0], aA);
        aB = fma2(pack2(x1, x1), wreg[1], aB);
        aC = fma2(pack2(x2, x2), wreg[2], aC);

        aD = fma2(pack2(d0.x, d0.x), wreg[3],  aD);
        aA = fma2(pack2(d0.y, d0.y), wreg[4],  aA);
        aB = fma2(pack2(d0.z, d0.z), wreg[5],  aB);
        aC = fma2(pack2(d0.w, d0.w), wreg[6],  aC);
        aD = fma2(pack2(d1.x, d1.x), wreg[7],  aD);
        aA = fma2(pack2(d1.y, d1.y), wreg[8],  aA);
        aB = fma2(pack2(d1.z, d1.z), wreg[9],  aB);
        aC = fma2(pack2(d1.w, d1.w), wreg[10], aC);
        aD = fma2(pack2(d2.x, d2.x), wreg[11], aD);
        aA = fma2(pack2(d2.y, d2.y), wreg[12], aA);
        aB = fma2(pack2(d2.z, d2.z), wreg[13], aB);
        aC = fma2(pack2(d2.w, d2.w), wreg[14], aC);
        aD = fma2(pack2(d3.x, d3.x), wreg[15], aD);
        aA = fma2(pack2(d3.y, d3.y), wreg[16], aA);
        aB = fma2(pack2(d3.z, d3.z), wreg[17], aB);
        aC = fma2(pack2(d3.w, d3.w), wreg[18], aC);

        aD = fma2(pack2(g0.x, g0.x), wreg[19], aD);
        aA = fma2(pack2(g0.y, g0.y), wreg[20], aA);
        aB = fma2(pack2(g0.z, g0.z), wreg[21], aB);
        aC = fma2(pack2(g0.w, g0.w), wreg[22], aC);
        aD = fma2(pack2(g1.x, g1.x), wreg[23], aD);
        aA = fma2(pack2(g1.y, g1.y), wreg[24], aA);
        aB = fma2(pack2(g1.z, g1.z), wreg[25], aB);
        aC = fma2(pack2(g1.w, g1.w), wreg[26], aC);
        aD = fma2(pack2(g2.x, g2.x), wreg[27], aD);
        aA = fma2(pack2(g2.y, g2.y), wreg[28], aA);
        aB = fma2(pack2(g2.z, g2.z), wreg[29], aB);
        aC = fma2(pack2(g2.w, g2.w), wreg[30], aC);
        aD = fma2(pack2(g3.x, g3.x), wreg[31], aD);
        aA = fma2(pack2(g3.y, g3.y), wreg[32], aA);
        aB = fma2(pack2(g3.z, g3.z), wreg[33], aB);
        aC = fma2(pack2(g3.w, g3.w), wreg[34], aC);

        float pa, pb, qa, qb, ra, rb, sa, sb;
        unpack2(aA, pa, pb);
        unpack2(aB, qa, qb);
        unpack2(aC, ra, rb);
        unpack2(aD, sa, sb);
        ull res = pack2((pa + qa) + (ra + sa), (pb + qb) + (rb + sb));
        *(ull*)(g_base1 + (size_t)j * 64 + 2 * lane) = res;
    }
}

// ================= main: mma.sync pure-fp16, register-pass L2->L3, 128 rows/CTA ====
// dyn smem: [0,13312) weight blob image; [13312,29696) A fp16 [128][128B] swizzled
#define SM_A    13312
#define KM_SMEM 29696

__global__ void __launch_bounds__(128, 5) k_mlp_mma(
    const int* __restrict__ exec_act_idx, float* __restrict__ out, int T) {

    extern __shared__ unsigned char sm8[];
    const uint32_t smb = smem_u32(sm8);
    const float* smallf = (const float*)(sm8 + 12288);
    const uint2* w2f = (const uint2*)sm8;                       // [kt*8+nt][lane]
    const uint2* w3f = (const uint2*)(sm8 + 8192);              // [kt*4+nt][lane]

    const int tid  = threadIdx.x;
    const int warp = tid >> 5;
    const int lane = tid & 31;
    const int q    = lane & 3;
    const int qr   = lane >> 2;
    const int rbase = warp * 32;

    // ---- copy prepped weights + smalls (13312 B = 832 uint4) ----
    {
        const uint4* src = (const uint4*)g_wblob;
        uint4* dst = (uint4*)sm8;
        #pragma unroll
        for (int it = 0; it < 7; it++) {
            int i = tid + it * 128;
            if (i < 832) dst[i] = src[i];
        }
    }
    __syncthreads();

    const int t  = blockIdx.x * 128 + tid;
    const int tt = (t < T) ? t : (T - 1);

    // ---- layer 1: h1 = relu(base1[j] + kf*W1L) -> fp16 -> smem A ----
    {
        int j   = g_rowjob[tt];
        float kf = (float)exec_act_idx[tt] * (1.0f / (float)NUM_EXEC);
        const float4* bp = (const float4*)(g_base1 + (size_t)j * 64);
        const int row = tid;
        #pragma unroll
        for (int c = 0; c < 8; c++) {
            float4 va = bp[2 * c];
            float4 vb = bp[2 * c + 1];
            float v0 = fmaxf(fmaf(kf, smallf[8 * c + 0], va.x), 0.0f);
            float v1 = fmaxf(fmaf(kf, smallf[8 * c + 1], va.y), 0.0f);
            float v2 = fmaxf(fmaf(kf, smallf[8 * c + 2], va.z), 0.0f);
            float v3 = fmaxf(fmaf(kf, smallf[8 * c + 3], va.w), 0.0f);
            float v4 = fmaxf(fmaf(kf, smallf[8 * c + 4], vb.x), 0.0f);
            float v5 = fmaxf(fmaf(kf, smallf[8 * c + 5], vb.y), 0.0f);
            float v6 = fmaxf(fmaf(kf, smallf[8 * c + 6], vb.z), 0.0f);
            float v7 = fmaxf(fmaf(kf, smallf[8 * c + 7], vb.w), 0.0f);
            uint4 w = make_uint4(packh2(v0, v1), packh2(v2, v3),
                                 packh2(v4, v5), packh2(v6, v7));
            uint32_t off = row * 128 + ((c ^ (row & 7)) << 4);
            *(uint4*)(sm8 + SM_A + off) = w;
        }
    }
    __syncthreads();

    // ---- layer 2: C[128,64] = Ah @ W2h ----
    float acc2[2][8][4];
    #pragma unroll
    for (int mt = 0; mt < 2; mt++)
        #pragma unroll
        for (int nt = 0; nt < 8; nt++)
            #pragma unroll
            for (int e = 0; e < 4; e++) acc2[mt][nt][e] = 0.0f;

    #pragma unroll
    for (int kt = 0; kt < 4; kt++) {
        uint32_t ah[2][4];
        #pragma unroll
        for (int mt = 0; mt < 2; mt++) {
            int r = rbase + mt * 16 + (lane & 15);
            uint32_t cb = kt * 32 + ((lane >> 4) << 4);
            uint32_t off = r * 128 + (cb ^ ((r & 7) << 4));
            ldmatrix4(ah[mt][0], ah[mt][1], ah[mt][2], ah[mt][3], smb + SM_A + off);
        }
        #pragma unroll
        for (int nt = 0; nt < 8; nt++) {
            uint2 b = w2f[(kt * 8 + nt) * 32 + lane];
            #pragma unroll
            for (int mt = 0; mt < 2; mt++) {
                float* d = acc2[mt][nt];
                mma16816(d[0], d[1], d[2], d[3], ah[mt][0], ah[mt][1], ah[mt][2], ah[mt][3], b.x, b.y);
            }
        }
    }

    // ---- register epilogue L2 + fragment pack: h2 = relu(C+b2) -> A fragments ----
    uint32_t a3f[2][4][4];   // [mt][kt][reg]
    #pragma unroll
    for (int mt = 0; mt < 2; mt++) {
        #pragma unroll
        for (int nt = 0; nt < 8; nt++) {
            int cn = nt * 8 + 2 * q;
            float bb0 = smallf[64 + cn], bb1 = smallf[64 + cn + 1];
            float v0 = fmaxf(acc2[mt][nt][0] + bb0, 0.0f);
            float v1 = fmaxf(acc2[mt][nt][1] + bb1, 0.0f);
            float v2 = fmaxf(acc2[mt][nt][2] + bb0, 0.0f);
            float v3 = fmaxf(acc2[mt][nt][3] + bb1, 0.0f);
            int kt = nt >> 1;
            int h  = (nt & 1) << 1;
            a3f[mt][kt][h + 0] = packh2(v0, v1);
            a3f[mt][kt][h + 1] = packh2(v2, v3);
        }
    }

    // ---- layer 3: C[128,32] = Ah @ W3h (A from registers) ----
    float acc3[2][4][4];
    #pragma unroll
    for (int mt = 0; mt < 2; mt++)
        #pragma unroll
        for (int nt = 0; nt < 4; nt++)
            #pragma unroll
            for (int e = 0; e < 4; e++) acc3[mt][nt][e] = 0.0f;

    #pragma unroll
    for (int kt = 0; kt < 4; kt++) {
        #pragma unroll
        for (int nt = 0; nt < 4; nt++) {
            uint2 b = w3f[(kt * 4 + nt) * 32 + lane];
            #pragma unroll
            for (int mt = 0; mt < 2; mt++) {
                float* d = acc3[mt][nt];
                mma16816(d[0], d[1], d[2], d[3],
                         a3f[mt][kt][0], a3f[mt][kt][1], a3f[mt][kt][2], a3f[mt][kt][3],
                         b.x, b.y);
            }
        }
    }

    // ---- epilogue L3: relu(C + b3) . W4, quad reduce, write ----
    #pragma unroll
    for (int mt = 0; mt < 2; mt++) {
        float sa = 0.0f, sb = 0.0f;
        #pragma unroll
        for (int nt = 0; nt < 4; nt++) {
            int cn = nt * 8 + 2 * q;
            float b0 = smallf[128 + cn], b1 = smallf[128 + cn + 1];
            float w0 = smallf[160 + cn], w1 = smallf[160 + cn + 1];
            sa = fmaf(fmaxf(acc3[mt][nt][0] + b0, 0.0f), w0, sa);
            sa = fmaf(fmaxf(acc3[mt][nt][1] + b1, 0.0f), w1, sa);
            sb = fmaf(fmaxf(acc3[mt][nt][2] + b0, 0.0f), w0, sb);
            sb = fmaf(fmaxf(acc3[mt][nt][3] + b1, 0.0f), w1, sb);
        }
        sa += __shfl_xor_sync(0xFFFFFFFFu, sa, 1);
        sa += __shfl_xor_sync(0xFFFFFFFFu, sa, 2);
        sb += __shfl_xor_sync(0xFFFFFFFFu, sb, 1);
        sb += __shfl_xor_sync(0xFFFFFFFFu, sb, 2);
        if (q == 0) {
            int ra = blockIdx.x * 128 + rbase + mt * 16 + qr;
            float b4v = smallf[192];
            if (ra < T)     out[ra]     = sa + b4v;
            if (ra + 8 < T) out[ra + 8] = sb + b4v;
        }
    }
}

// ================= launcher =================
extern "C" void kernel_launch(void* const* d_in, const int* in_sizes, int n_in,
                              void* d_out, int out_size) {
    const float* x          = (const float*)d_in[0];
    const float* h_dag      = (const float*)d_in[1];
    const float* h_glob     = (const float*)d_in[2];
    const int* ptr          = (const int*)d_in[3];
    const int* job_idx      = (const int*)d_in[4];
    const int* num_exec     = (const int*)d_in[5];
    const int* exec_aidx    = (const int*)d_in[6];
    const float* W1 = (const float*)d_in[7];
    const float* b1 = (const float*)d_in[8];
    const float* W2 = (const float*)d_in[9];
    const float* b2 = (const float*)d_in[10];
    const float* W3 = (const float*)d_in[11];
    const float* b3 = (const float*)d_in[12];
    const float* W4 = (const float*)d_in[13];
    const float* b4 = (const float*)d_in[14];
    float* out = (float*)d_out;

    int J = in_sizes[4];
    int T = in_sizes[6];

    cudaFuncSetAttribute(k_mlp_mma, cudaFuncAttributeMaxDynamicSharedMemorySize, KM_SMEM);

    int nblocks256 = (J + 255) / 256;

    k_p1<<<nblocks256 + 7, 256>>>(job_idx, num_exec, J, W1, W2, b2, W3, b3, W4, b4);
    k_scan<<<1, 512>>>(nblocks256);
    k_p3<<<nblocks256, 256>>>(J);
    k_base1<<<(J + 63) / 64, 256>>>(x, h_dag, h_glob, ptr, job_idx, W1, b1, J);
    k_mlp_mma<<<(T + 127) / 128, 128, KM_SMEM>>>(exec_aidx, out, T);
}

// round 14
// speedup vs baseline: 1.0570x; 1.0570x over previous
#include <cuda_runtime.h>
#include <cuda_fp16.h>
#include <stdint.h>

// ---------------- problem constants ----------------
#define NUM_EXEC   50
#define MAXB       60000
#define MAXT       (MAXB * NUM_EXEC)

typedef unsigned long long ull;

// ---------------- device scratch ----------------
__device__ int   g_nsel[MAXB];
__device__ int   g_blocksum[512];
__device__ int   g_rowjob[MAXT];
__device__ float g_base1[(size_t)MAXB * 64];
// prepped weight blob (exact smem image), FRAGMENT-ORDERED B, pure fp16:
//  [0,8192)      W2 frags: kt(4) x nt(8) x lane(32): uint2 {b0,b1}
//  [8192,12288)  W3 frags: kt(4) x nt(4) x lane(32): uint2
//  [12288,13312) fp32 smalls: W1L[64] b2[64] b3[32] W4[32] b4[1]
__device__ __align__(16) unsigned char g_wblob[13312];

// ---------------- helpers ----------------
__device__ __forceinline__ ull fma2(ull a, ull b, ull c) {
    ull d;
    asm("fma.rn.f32x2 %0, %1, %2, %3;" : "=l"(d) : "l"(a), "l"(b), "l"(c));
    return d;
}
__device__ __forceinline__ ull pack2(float a, float b) {
    ull r;
    asm("mov.b64 %0, {%1,%2};" : "=l"(r) : "f"(a), "f"(b));
    return r;
}
__device__ __forceinline__ void unpack2(ull v, float& a, float& b) {
    asm("mov.b64 {%0,%1}, %2;" : "=f"(a), "=f"(b) : "l"(v));
}
__device__ __forceinline__ uint32_t smem_u32(const void* p) {
    uint32_t a;
    asm("{ .reg .u64 t; cvta.to.shared.u64 t, %1; cvt.u32.u64 %0, t; }" : "=r"(a) : "l"(p));
    return a;
}
// pack (lo_elem, hi_elem) -> f16x2, lo_elem in low 16 bits
__device__ __forceinline__ uint32_t packh2(float lov, float hiv) {
    uint32_t r;
    asm("cvt.rn.f16x2.f32 %0, %1, %2;" : "=r"(r) : "f"(hiv), "f"(lov));
    return r;
}
__device__ __forceinline__ void ldmatrix4(uint32_t& a0, uint32_t& a1, uint32_t& a2,
                                          uint32_t& a3, uint32_t addr) {
    asm volatile("ldmatrix.sync.aligned.m8n8.x4.shared.b16 {%0,%1,%2,%3}, [%4];"
                 : "=r"(a0), "=r"(a1), "=r"(a2), "=r"(a3) : "r"(addr));
}
__device__ __forceinline__ void mma16816(float& d0, float& d1, float& d2, float& d3,
                                         uint32_t a0, uint32_t a1, uint32_t a2, uint32_t a3,
                                         uint32_t b0, uint32_t b1) {
    asm volatile("mma.sync.aligned.m16n8k16.row.col.f32.f16.f16.f32 "
                 "{%0,%1,%2,%3}, {%4,%5,%6,%7}, {%8,%9}, {%0,%1,%2,%3};"
                 : "+f"(d0), "+f"(d1), "+f"(d2), "+f"(d3)
                 : "r"(a0), "r"(a1), "r"(a2), "r"(a3), "r"(b0), "r"(b1));
}
// XOR-16B swizzle for 128B rows (A tile only)
__device__ __host__ __forceinline__ uint32_t sw128(uint32_t b) {
    return b ^ ((b >> 3) & 0x70);
}

// ================= prologue 1: nsel gather + block sums, FUSED with weight prep ======
__global__ void k_p1(const int* __restrict__ job_indices,
                     const int* __restrict__ num_exec_acts, int J,
                     const float* __restrict__ W1, const float* __restrict__ W2,
                     const float* __restrict__ b2, const float* __restrict__ W3,
                     const float* __restrict__ b3, const float* __restrict__ W4,
                     const float* __restrict__ b4) {
    int nb = (J + 255) >> 8;
    if ((int)blockIdx.x < nb) {
        __shared__ int s[256];
        int j = blockIdx.x * 256 + threadIdx.x;
        int v = 0;
        if (j < J) { v = num_exec_acts[job_indices[j]]; g_nsel[j] = v; }
        s[threadIdx.x] = v;
        __syncthreads();
        #pragma unroll
        for (int o = 128; o > 0; o >>= 1) {
            if (threadIdx.x < o) s[threadIdx.x] += s[threadIdx.x + o];
            __syncthreads();
        }
        if (threadIdx.x == 0) g_blocksum[blockIdx.x] = s[0];
    } else {
        int tid = (blockIdx.x - nb) * 256 + threadIdx.x;
        if (tid < 1024) {                 // W2 fragments: kt(4) x nt(8) x lane(32)
            int kt = tid >> 8, nt = (tid >> 5) & 7, lane = tid & 31;
            int q = lane & 3, qr = lane >> 2;
            int n = nt * 8 + qr;
            int k0 = kt * 16 + 2 * q;
            uint2 v;
            v.x = packh2(W2[(k0    ) * 64 + n], W2[(k0 + 1) * 64 + n]);
            v.y = packh2(W2[(k0 + 8) * 64 + n], W2[(k0 + 9) * 64 + n]);
            ((uint2*)g_wblob)[tid] = v;
        } else if (tid < 1536) {          // W3 fragments: kt(4) x nt(4) x lane(32)
            int e = tid - 1024;
            int kt = e >> 7, nt = (e >> 5) & 3, lane = e & 31;
            int q = lane & 3, qr = lane >> 2;
            int n = nt * 8 + qr;
            int k0 = kt * 16 + 2 * q;
            uint2 v;
            v.x = packh2(W3[(k0    ) * 32 + n], W3[(k0 + 1) * 32 + n]);
            v.y = packh2(W3[(k0 + 8) * 32 + n], W3[(k0 + 9) * 32 + n]);
            ((uint2*)g_wblob)[1024 + e] = v;
        } else if (tid < 1536 + 256) {
            int i = tid - 1536;
            float* s = (float*)(g_wblob + 12288);
            if (i < 64)       s[i] = W1[35 * 64 + i];
            else if (i < 128) s[i] = b2[i - 64];
            else if (i < 160) s[i] = b3[i - 128];
            else if (i < 192) s[i] = W4[i - 160];
            else if (i == 192) s[192] = b4[0];
        }
    }
}

// ================= prologue 2: per-job start + row->job fill, scan FUSED in ==========
// Each block locally scans the (<=256) block sums — no separate k_scan launch.
__global__ void k_p3(int J) {
    __shared__ int s[256];
    __shared__ int bs[256];
    int tid = threadIdx.x;
    int nb = (J + 255) >> 8;
    bs[tid] = (tid < nb) ? g_blocksum[tid] : 0;
    int j = blockIdx.x * 256 + tid;
    int v = (j < J) ? g_nsel[j] : 0;
    s[tid] = v;
    __syncthreads();
    // dual Hillis-Steele scans (block sums + in-block counts), shared sync points
    for (int o = 1; o < 256; o <<= 1) {
        int tb = (tid >= o) ? bs[tid - o] : 0;
        int ts = (tid >= o) ? s[tid - o]  : 0;
        __syncthreads();
        bs[tid] += tb;
        s[tid]  += ts;
        __syncthreads();
    }
    if (j < J) {
        int blockpre = (blockIdx.x == 0) ? 0 : bs[blockIdx.x - 1];
        int start = (s[tid] - v) + blockpre;
        for (int k = 0; k < v; k++) g_rowjob[start + k] = j;
    }
}

// ================= base1 (R12 version): smem W1, 64 jobs/block, 2 jobs + 2 chains ====
__global__ void __launch_bounds__(256) k_base1(
    const float* __restrict__ x, const float* __restrict__ h_dag,
    const float* __restrict__ h_glob,
    const int* __restrict__ ptr, const int* __restrict__ jidx,
    const float* __restrict__ W1, const float* __restrict__ b1, int J) {
    __shared__ __align__(16) float sW1[35 * 64];
    __shared__ __align__(16) float sB1[64];
    for (int i = threadIdx.x; i < 35 * 64; i += blockDim.x) sW1[i] = W1[i];
    for (int i = threadIdx.x; i < 64; i += blockDim.x)      sB1[i] = b1[i];
    __syncthreads();

    const int warp = threadIdx.x >> 5;
    const int lane = threadIdx.x & 31;
    const int jbase = blockIdx.x * 64 + warp;

    #pragma unroll 1
    for (int it = 0; it < 4; it++) {
        int j0 = jbase + it * 16;
        if (j0 >= J) break;
        int j1 = j0 + 8;
        bool has1 = (j1 < J);
        int j1c = has1 ? j1 : j0;

        int ji0 = jidx[j0], ji1 = jidx[j1c];
        const float* xr0 = x + (long long)ptr[ji0] * 5;
        const float* xr1 = x + (long long)ptr[ji1] * 5;
        const float* hd0 = h_dag + (long long)ji0 * 16;
        const float* hd1 = h_dag + (long long)ji1 * 16;
        const float* hg0 = h_glob + (long long)j0 * 16;
        const float* hg1 = h_glob + (long long)j1c * 16;

        ull bias = pack2(sB1[2 * lane], sB1[2 * lane + 1]);
        ull zero = pack2(0.0f, 0.0f);
        ull a0A = bias, a0B = zero;
        ull a1A = bias, a1B = zero;

        #pragma unroll
        for (int i = 0; i < 3; i++) {
            ull w = *(const ull*)&sW1[i * 64 + 2 * lane];
            float v0 = xr0[i], v1 = xr1[i];
            a0A = fma2(pack2(v0, v0), w, a0A);
            a1A = fma2(pack2(v1, v1), w, a1A);
        }
        #pragma unroll
        for (int i = 0; i < 16; i++) {
            ull w = *(const ull*)&sW1[(3 + i) * 64 + 2 * lane];
            float v0 = hd0[i], v1 = hd1[i];
            if (i & 1) { a0B = fma2(pack2(v0, v0), w, a0B); a1B = fma2(pack2(v1, v1), w, a1B); }
            else       { a0A = fma2(pack2(v0, v0), w, a0A); a1A = fma2(pack2(v1, v1), w, a1A); }
        }
        #pragma unroll
        for (int i = 0; i < 16; i++) {
            ull w = *(const ull*)&sW1[(19 + i) * 64 + 2 * lane];
            float v0 = hg0[i], v1 = hg1[i];
            if (i & 1) { a0B = fma2(pack2(v0, v0), w, a0B); a1B = fma2(pack2(v1, v1), w, a1B); }
            else       { a0A = fma2(pack2(v0, v0), w, a0A); a1A = fma2(pack2(v1, v1), w, a1A); }
        }

        float xa, xb, ya, yb;
        unpack2(a0A, xa, xb);
        unpack2(a0B, ya, yb);
        float* d0 = g_base1 + (size_t)j0 * 64 + 2 * lane;
        d0[0] = xa + ya;
        d0[1] = xb + yb;
        if (has1) {
            unpack2(a1A, xa, xb);
            unpack2(a1B, ya, yb);
            float* d1 = g_base1 + (size_t)j1 * 64 + 2 * lane;
            d1[0] = xa + ya;
            d1[1] = xb + yb;
        }
    }
}

// ================= main: mma.sync pure-fp16, register-pass L2->L3, 128 rows/CTA ====
// dyn smem: [0,13312) weight blob image; [13312,29696) A fp16 [128][128B] swizzled
#define SM_A    13312
#define KM_SMEM 29696

__global__ void __launch_bounds__(128, 5) k_mlp_mma(
    const int* __restrict__ exec_act_idx, float* __restrict__ out, int T) {

    extern __shared__ unsigned char sm8[];
    const uint32_t smb = smem_u32(sm8);
    const float* smallf = (const float*)(sm8 + 12288);
    const uint2* w2f = (const uint2*)sm8;                       // [kt*8+nt][lane]
    const uint2* w3f = (const uint2*)(sm8 + 8192);              // [kt*4+nt][lane]

    const int tid  = threadIdx.x;
    const int warp = tid >> 5;
    const int lane = tid & 31;
    const int q    = lane & 3;
    const int qr   = lane >> 2;
    const int rbase = warp * 32;

    // ---- copy prepped weights + smalls (13312 B = 832 uint4) ----
    {
        const uint4* src = (const uint4*)g_wblob;
        uint4* dst = (uint4*)sm8;
        #pragma unroll
        for (int it = 0; it < 7; it++) {
            int i = tid + it * 128;
            if (i < 832) dst[i] = src[i];
        }
    }
    __syncthreads();

    const int t  = blockIdx.x * 128 + tid;
    const int tt = (t < T) ? t : (T - 1);

    // ---- layer 1: h1 = relu(base1[j] + kf*W1L) -> fp16 -> smem A ----
    {
        int j   = g_rowjob[tt];
        float kf = (float)exec_act_idx[tt] * (1.0f / (float)NUM_EXEC);
        const float4* bp = (const float4*)(g_base1 + (size_t)j * 64);
        const int row = tid;
        #pragma unroll
        for (int c = 0; c < 8; c++) {
            float4 va = bp[2 * c];
            float4 vb = bp[2 * c + 1];
            float v0 = fmaxf(fmaf(kf, smallf[8 * c + 0], va.x), 0.0f);
            float v1 = fmaxf(fmaf(kf, smallf[8 * c + 1], va.y), 0.0f);
            float v2 = fmaxf(fmaf(kf, smallf[8 * c + 2], va.z), 0.0f);
            float v3 = fmaxf(fmaf(kf, smallf[8 * c + 3], va.w), 0.0f);
            float v4 = fmaxf(fmaf(kf, smallf[8 * c + 4], vb.x), 0.0f);
            float v5 = fmaxf(fmaf(kf, smallf[8 * c + 5], vb.y), 0.0f);
            float v6 = fmaxf(fmaf(kf, smallf[8 * c + 6], vb.z), 0.0f);
            float v7 = fmaxf(fmaf(kf, smallf[8 * c + 7], vb.w), 0.0f);
            uint4 w = make_uint4(packh2(v0, v1), packh2(v2, v3),
                                 packh2(v4, v5), packh2(v6, v7));
            uint32_t off = row * 128 + ((c ^ (row & 7)) << 4);
            *(uint4*)(sm8 + SM_A + off) = w;
        }
    }
    __syncthreads();

    // ---- layer 2: C[128,64] = Ah @ W2h ----
    float acc2[2][8][4];
    #pragma unroll
    for (int mt = 0; mt < 2; mt++)
        #pragma unroll
        for (int nt = 0; nt < 8; nt++)
            #pragma unroll
            for (int e = 0; e < 4; e++) acc2[mt][nt][e] = 0.0f;

    #pragma unroll
    for (int kt = 0; kt < 4; kt++) {
        uint32_t ah[2][4];
        #pragma unroll
        for (int mt = 0; mt < 2; mt++) {
            int r = rbase + mt * 16 + (lane & 15);
            uint32_t cb = kt * 32 + ((lane >> 4) << 4);
            uint32_t off = r * 128 + (cb ^ ((r & 7) << 4));
            ldmatrix4(ah[mt][0], ah[mt][1], ah[mt][2], ah[mt][3], smb + SM_A + off);
        }
        #pragma unroll
        for (int nt = 0; nt < 8; nt++) {
            uint2 b = w2f[(kt * 8 + nt) * 32 + lane];
            #pragma unroll
            for (int mt = 0; mt < 2; mt++) {
                float* d = acc2[mt][nt];
                mma16816(d[0], d[1], d[2], d[3], ah[mt][0], ah[mt][1], ah[mt][2], ah[mt][3], b.x, b.y);
            }
        }
    }

    // ---- register epilogue L2 + fragment pack: h2 = relu(C+b2) -> A fragments ----
    uint32_t a3f[2][4][4];   // [mt][kt][reg]
    #pragma unroll
    for (int mt = 0; mt < 2; mt++) {
        #pragma unroll
        for (int nt = 0; nt < 8; nt++) {
            int cn = nt * 8 + 2 * q;
            float bb0 = smallf[64 + cn], bb1 = smallf[64 + cn + 1];
            float v0 = fmaxf(acc2[mt][nt][0] + bb0, 0.0f);
            float v1 = fmaxf(acc2[mt][nt][1] + bb1, 0.0f);
            float v2 = fmaxf(acc2[mt][nt][2] + bb0, 0.0f);
            float v3 = fmaxf(acc2[mt][nt][3] + bb1, 0.0f);
            int kt = nt >> 1;
            int h  = (nt & 1) << 1;
            a3f[mt][kt][h + 0] = packh2(v0, v1);
            a3f[mt][kt][h + 1] = packh2(v2, v3);
        }
    }

    // ---- layer 3: C[128,32] = Ah @ W3h (A from registers) ----
    float acc3[2][4][4];
    #pragma unroll
    for (int mt = 0; mt < 2; mt++)
        #pragma unroll
        for (int nt = 0; nt < 4; nt++)
            #pragma unroll
            for (int e = 0; e < 4; e++) acc3[mt][nt][e] = 0.0f;

    #pragma unroll
    for (int kt = 0; kt < 4; kt++) {
        #pragma unroll
        for (int nt = 0; nt < 4; nt++) {
            uint2 b = w3f[(kt * 4 + nt) * 32 + lane];
            #pragma unroll
            for (int mt = 0; mt < 2; mt++) {
                float* d = acc3[mt][nt];
                mma16816(d[0], d[1], d[2], d[3],
                         a3f[mt][kt][0], a3f[mt][kt][1], a3f[mt][kt][2], a3f[mt][kt][3],
                         b.x, b.y);
            }
        }
    }

    // ---- epilogue L3: relu(C + b3) . W4, quad reduce, write ----
    #pragma unroll
    for (int mt = 0; mt < 2; mt++) {
        float sa = 0.0f, sb = 0.0f;
        #pragma unroll
        for (int nt = 0; nt < 4; nt++) {
            int cn = nt * 8 + 2 * q;
            float b0 = smallf[128 + cn], b1 = smallf[128 + cn + 1];
            float w0 = smallf[160 + cn], w1 = smallf[160 + cn + 1];
            sa = fmaf(fmaxf(acc3[mt][nt][0] + b0, 0.0f), w0, sa);
            sa = fmaf(fmaxf(acc3[mt][nt][1] + b1, 0.0f), w1, sa);
            sb = fmaf(fmaxf(acc3[mt][nt][2] + b0, 0.0f), w0, sb);
            sb = fmaf(fmaxf(acc3[mt][nt][3] + b1, 0.0f), w1, sb);
        }
        sa += __shfl_xor_sync(0xFFFFFFFFu, sa, 1);
        sa += __shfl_xor_sync(0xFFFFFFFFu, sa, 2);
        sb += __shfl_xor_sync(0xFFFFFFFFu, sb, 1);
        sb += __shfl_xor_sync(0xFFFFFFFFu, sb, 2);
        if (q == 0) {
            int ra = blockIdx.x * 128 + rbase + mt * 16 + qr;
            float b4v = smallf[192];
            if (ra < T)     out[ra]     = sa + b4v;
            if (ra + 8 < T) out[ra + 8] = sb + b4v;
        }
    }
}

// ================= launcher (fork-join: base1 overlaps the scan chain) =============
extern "C" void kernel_launch(void* const* d_in, const int* in_sizes, int n_in,
                              void* d_out, int out_size) {
    const float* x          = (const float*)d_in[0];
    const float* h_dag      = (const float*)d_in[1];
    const float* h_glob     = (const float*)d_in[2];
    const int* ptr          = (const int*)d_in[3];
    const int* job_idx      = (const int*)d_in[4];
    const int* num_exec     = (const int*)d_in[5];
    const int* exec_aidx    = (const int*)d_in[6];
    const float* W1 = (const float*)d_in[7];
    const float* b1 = (const float*)d_in[8];
    const float* W2 = (const float*)d_in[9];
    const float* b2 = (const float*)d_in[10];
    const float* W3 = (const float*)d_in[11];
    const float* b3 = (const float*)d_in[12];
    const float* W4 = (const float*)d_in[13];
    const float* b4 = (const float*)d_in[14];
    float* out = (float*)d_out;

    int J = in_sizes[4];
    int T = in_sizes[6];

    static cudaStream_t s1 = nullptr;
    static cudaEvent_t evF = nullptr, evJ = nullptr;
    if (s1 == nullptr) {
        cudaStreamCreateWithFlags(&s1, cudaStreamNonBlocking);
        cudaEventCreateWithFlags(&evF, cudaEventDisableTiming);
        cudaEventCreateWithFlags(&evJ, cudaEventDisableTiming);
        cudaFuncSetAttribute(k_mlp_mma, cudaFuncAttributeMaxDynamicSharedMemorySize, KM_SMEM);
    }

    int nblocks256 = (J + 255) / 256;

    // fork: base1 on side stream (depends only on inputs)
    cudaEventRecord(evF, 0);
    cudaStreamWaitEvent(s1, evF, 0);
    k_base1<<<(J + 63) / 64, 256, 0, s1>>>(x, h_dag, h_glob, ptr, job_idx, W1, b1, J);
    cudaEventRecord(evJ, s1);

    // main stream: scan chain + weight prep
    k_p1<<<nblocks256 + 7, 256>>>(job_idx, num_exec, J, W1, W2, b2, W3, b3, W4, b4);
    k_p3<<<nblocks256, 256>>>(J);

    // join, then main MLP
    cudaStreamWaitEvent(0, evJ, 0);
    k_mlp_mma<<<(T + 127) / 128, 128, KM_SMEM>>>(exec_aidx, out, T);
}

// round 15
// speedup vs baseline: 1.0723x; 1.0145x over previous
#include <cuda_runtime.h>
#include <cuda_fp16.h>
#include <stdint.h>

// ---------------- problem constants ----------------
#define NUM_EXEC   50
#define MAXB       60000
#define MAXT       (MAXB * NUM_EXEC)

typedef unsigned long long ull;

// ---------------- device scratch ----------------
__device__ int   g_nsel[MAXB];
__device__ int   g_blocksum[512];
__device__ int   g_rowjob[MAXT];
__device__ float g_base1[(size_t)MAXB * 64];
// prepped weight blob (exact smem image), FRAGMENT-ORDERED B, pure fp16:
//  [0,8192)      W2 frags: kt(4) x nt(8) x lane(32): uint2 {b0,b1}
//  [8192,12288)  W3 frags: kt(4) x nt(4) x lane(32): uint2
//  [12288,13312) fp32 smalls: W1L[64] b2[64] b3[32] W4[32] b4[1]
__device__ __align__(16) unsigned char g_wblob[13312];

// ---------------- helpers ----------------
__device__ __forceinline__ ull fma2(ull a, ull b, ull c) {
    ull d;
    asm("fma.rn.f32x2 %0, %1, %2, %3;" : "=l"(d) : "l"(a), "l"(b), "l"(c));
    return d;
}
__device__ __forceinline__ ull pack2(float a, float b) {
    ull r;
    asm("mov.b64 %0, {%1,%2};" : "=l"(r) : "f"(a), "f"(b));
    return r;
}
__device__ __forceinline__ void unpack2(ull v, float& a, float& b) {
    asm("mov.b64 {%0,%1}, %2;" : "=f"(a), "=f"(b) : "l"(v));
}
__device__ __forceinline__ uint32_t smem_u32(const void* p) {
    uint32_t a;
    asm("{ .reg .u64 t; cvta.to.shared.u64 t, %1; cvt.u32.u64 %0, t; }" : "=r"(a) : "l"(p));
    return a;
}
// pack (lo_elem, hi_elem) -> f16x2, lo_elem in low 16 bits
__device__ __forceinline__ uint32_t packh2(float lov, float hiv) {
    uint32_t r;
    asm("cvt.rn.f16x2.f32 %0, %1, %2;" : "=r"(r) : "f"(hiv), "f"(lov));
    return r;
}
__device__ __forceinline__ void ldmatrix4(uint32_t& a0, uint32_t& a1, uint32_t& a2,
                                          uint32_t& a3, uint32_t addr) {
    asm volatile("ldmatrix.sync.aligned.m8n8.x4.shared.b16 {%0,%1,%2,%3}, [%4];"
                 : "=r"(a0), "=r"(a1), "=r"(a2), "=r"(a3) : "r"(addr));
}
__device__ __forceinline__ void mma16816(float& d0, float& d1, float& d2, float& d3,
                                         uint32_t a0, uint32_t a1, uint32_t a2, uint32_t a3,
                                         uint32_t b0, uint32_t b1) {
    asm volatile("mma.sync.aligned.m16n8k16.row.col.f32.f16.f16.f32 "
                 "{%0,%1,%2,%3}, {%4,%5,%6,%7}, {%8,%9}, {%0,%1,%2,%3};"
                 : "+f"(d0), "+f"(d1), "+f"(d2), "+f"(d3)
                 : "r"(a0), "r"(a1), "r"(a2), "r"(a3), "r"(b0), "r"(b1));
}
// XOR-16B swizzle for 128B rows (A tile only)
__device__ __host__ __forceinline__ uint32_t sw128(uint32_t b) {
    return b ^ ((b >> 3) & 0x70);
}

// ================= prologue 1: nsel gather + block sums, FUSED with weight prep ======
__global__ void k_p1(const int* __restrict__ job_indices,
                     const int* __restrict__ num_exec_acts, int J,
                     const float* __restrict__ W1, const float* __restrict__ W2,
                     const float* __restrict__ b2, const float* __restrict__ W3,
                     const float* __restrict__ b3, const float* __restrict__ W4,
                     const float* __restrict__ b4) {
    int nb = (J + 255) >> 8;
    if ((int)blockIdx.x < nb) {
        __shared__ int s[256];
        int j = blockIdx.x * 256 + threadIdx.x;
        int v = 0;
        if (j < J) { v = num_exec_acts[job_indices[j]]; g_nsel[j] = v; }
        s[threadIdx.x] = v;
        __syncthreads();
        #pragma unroll
        for (int o = 128; o > 0; o >>= 1) {
            if (threadIdx.x < o) s[threadIdx.x] += s[threadIdx.x + o];
            __syncthreads();
        }
        if (threadIdx.x == 0) g_blocksum[blockIdx.x] = s[0];
    } else {
        int tid = (blockIdx.x - nb) * 256 + threadIdx.x;
        if (tid < 1024) {                 // W2 fragments: kt(4) x nt(8) x lane(32)
            int kt = tid >> 8, nt = (tid >> 5) & 7, lane = tid & 31;
            int q = lane & 3, qr = lane >> 2;
            int n = nt * 8 + qr;
            int k0 = kt * 16 + 2 * q;
            uint2 v;
            v.x = packh2(W2[(k0    ) * 64 + n], W2[(k0 + 1) * 64 + n]);
            v.y = packh2(W2[(k0 + 8) * 64 + n], W2[(k0 + 9) * 64 + n]);
            ((uint2*)g_wblob)[tid] = v;
        } else if (tid < 1536) {          // W3 fragments: kt(4) x nt(4) x lane(32)
            int e = tid - 1024;
            int kt = e >> 7, nt = (e >> 5) & 3, lane = e & 31;
            int q = lane & 3, qr = lane >> 2;
            int n = nt * 8 + qr;
            int k0 = kt * 16 + 2 * q;
            uint2 v;
            v.x = packh2(W3[(k0    ) * 32 + n], W3[(k0 + 1) * 32 + n]);
            v.y = packh2(W3[(k0 + 8) * 32 + n], W3[(k0 + 9) * 32 + n]);
            ((uint2*)g_wblob)[1024 + e] = v;
        } else if (tid < 1536 + 256) {
            int i = tid - 1536;
            float* s = (float*)(g_wblob + 12288);
            if (i < 64)       s[i] = W1[35 * 64 + i];
            else if (i < 128) s[i] = b2[i - 64];
            else if (i < 160) s[i] = b3[i - 128];
            else if (i < 192) s[i] = W4[i - 160];
            else if (i == 192) s[192] = b4[0];
        }
    }
}

// ================= prologue 2: per-job start + row->job fill, scan FUSED in ==========
__global__ void k_p3(int J) {
    __shared__ int s[256];
    __shared__ int bs[256];
    int tid = threadIdx.x;
    int nb = (J + 255) >> 8;
    bs[tid] = (tid < nb) ? g_blocksum[tid] : 0;
    int j = blockIdx.x * 256 + tid;
    int v = (j < J) ? g_nsel[j] : 0;
    s[tid] = v;
    __syncthreads();
    for (int o = 1; o < 256; o <<= 1) {
        int tb = (tid >= o) ? bs[tid - o] : 0;
        int ts = (tid >= o) ? s[tid - o]  : 0;
        __syncthreads();
        bs[tid] += tb;
        s[tid]  += ts;
        __syncthreads();
    }
    if (j < J) {
        int blockpre = (blockIdx.x == 0) ? 0 : bs[blockIdx.x - 1];
        int start = (s[tid] - v) + blockpre;
        for (int k = 0; k < v; k++) g_rowjob[start + k] = j;
    }
}

// ================= base1: smem W1, 64 jobs/block, 4 jobs in flight x 2 chains ========
__global__ void __launch_bounds__(256) k_base1(
    const float* __restrict__ x, const float* __restrict__ h_dag,
    const float* __restrict__ h_glob,
    const int* __restrict__ ptr, const int* __restrict__ jidx,
    const float* __restrict__ W1, const float* __restrict__ b1, int J) {
    __shared__ __align__(16) float sW1[35 * 64];
    __shared__ __align__(16) float sB1[64];
    for (int i = threadIdx.x; i < 35 * 64; i += blockDim.x) sW1[i] = W1[i];
    for (int i = threadIdx.x; i < 64; i += blockDim.x)      sB1[i] = b1[i];
    __syncthreads();

    const int warp = threadIdx.x >> 5;
    const int lane = threadIdx.x & 31;
    const int jbase = blockIdx.x * 64 + warp;

    #pragma unroll 1
    for (int it = 0; it < 2; it++) {
        int jm = jbase + it * 32;
        if (jm >= J) break;

        bool hv[4];
        const float *xr[4], *hd[4], *hg[4];
        #pragma unroll
        for (int c = 0; c < 4; c++) {
            int j = jm + c * 8;
            hv[c] = (j < J);
            int jc = hv[c] ? j : jm;
            int ji = jidx[jc];
            xr[c] = x + (long long)ptr[ji] * 5;
            hd[c] = h_dag + (long long)ji * 16;
            hg[c] = h_glob + (long long)jc * 16;
        }

        ull bias = pack2(sB1[2 * lane], sB1[2 * lane + 1]);
        ull zero = pack2(0.0f, 0.0f);
        ull aA[4], aB[4];
        #pragma unroll
        for (int c = 0; c < 4; c++) { aA[c] = bias; aB[c] = zero; }

        #pragma unroll
        for (int i = 0; i < 3; i++) {
            ull w = *(const ull*)&sW1[i * 64 + 2 * lane];
            #pragma unroll
            for (int c = 0; c < 4; c++) {
                float v = xr[c][i];
                aA[c] = fma2(pack2(v, v), w, aA[c]);
            }
        }
        #pragma unroll
        for (int i = 0; i < 16; i++) {
            ull w = *(const ull*)&sW1[(3 + i) * 64 + 2 * lane];
            #pragma unroll
            for (int c = 0; c < 4; c++) {
                float v = hd[c][i];
                if (i & 1) aB[c] = fma2(pack2(v, v), w, aB[c]);
                else       aA[c] = fma2(pack2(v, v), w, aA[c]);
            }
        }
        #pragma unroll
        for (int i = 0; i < 16; i++) {
            ull w = *(const ull*)&sW1[(19 + i) * 64 + 2 * lane];
            #pragma unroll
            for (int c = 0; c < 4; c++) {
                float v = hg[c][i];
                if (i & 1) aB[c] = fma2(pack2(v, v), w, aB[c]);
                else       aA[c] = fma2(pack2(v, v), w, aA[c]);
            }
        }

        #pragma unroll
        for (int c = 0; c < 4; c++) {
            if (!hv[c]) continue;
            float xa, xb, ya, yb;
            unpack2(aA[c], xa, xb);
            unpack2(aB[c], ya, yb);
            float* d = g_base1 + (size_t)(jm + c * 8) * 64 + 2 * lane;
            d[0] = xa + ya;
            d[1] = xb + yb;
        }
    }
}

// ================= main: mma.sync pure-fp16, register-pass L2->L3, 128 rows/CTA ====
// dyn smem: [0,13312) weight blob image; [13312,29696) A fp16 [128][128B] swizzled
#define SM_A    13312
#define KM_SMEM 29696

__global__ void __launch_bounds__(128, 5) k_mlp_mma(
    const int* __restrict__ exec_act_idx, float* __restrict__ out, int T) {

    extern __shared__ unsigned char sm8[];
    const uint32_t smb = smem_u32(sm8);
    const float* smallf = (const float*)(sm8 + 12288);
    const uint2* w2f = (const uint2*)sm8;                       // [kt*8+nt][lane]
    const uint2* w3f = (const uint2*)(sm8 + 8192);              // [kt*4+nt][lane]

    const int tid  = threadIdx.x;
    const int warp = tid >> 5;
    const int lane = tid & 31;
    const int q    = lane & 3;
    const int qr   = lane >> 2;
    const int rbase = warp * 32;

    // ---- copy prepped weights + smalls (13312 B = 832 uint4) ----
    {
        const uint4* src = (const uint4*)g_wblob;
        uint4* dst = (uint4*)sm8;
        #pragma unroll
        for (int it = 0; it < 7; it++) {
            int i = tid + it * 128;
            if (i < 832) dst[i] = src[i];
        }
    }
    __syncthreads();

    const int t  = blockIdx.x * 128 + tid;
    const int tt = (t < T) ? t : (T - 1);

    // ---- layer 1: h1 = relu(base1[j] + kf*W1L) -> fp16 -> smem A (float4 W1L) ----
    {
        int j   = g_rowjob[tt];
        float kf = (float)exec_act_idx[tt] * (1.0f / (float)NUM_EXEC);
        const float4* bp = (const float4*)(g_base1 + (size_t)j * 64);
        const float4* wl = (const float4*)smallf;
        const int row = tid;
        #pragma unroll
        for (int c = 0; c < 8; c++) {
            float4 va = bp[2 * c];
            float4 vb = bp[2 * c + 1];
            float4 wa = wl[2 * c];
            float4 wb = wl[2 * c + 1];
            float v0 = fmaxf(fmaf(kf, wa.x, va.x), 0.0f);
            float v1 = fmaxf(fmaf(kf, wa.y, va.y), 0.0f);
            float v2 = fmaxf(fmaf(kf, wa.z, va.z), 0.0f);
            float v3 = fmaxf(fmaf(kf, wa.w, va.w), 0.0f);
            float v4 = fmaxf(fmaf(kf, wb.x, vb.x), 0.0f);
            float v5 = fmaxf(fmaf(kf, wb.y, vb.y), 0.0f);
            float v6 = fmaxf(fmaf(kf, wb.z, vb.z), 0.0f);
            float v7 = fmaxf(fmaf(kf, wb.w, vb.w), 0.0f);
            uint4 w = make_uint4(packh2(v0, v1), packh2(v2, v3),
                                 packh2(v4, v5), packh2(v6, v7));
            uint32_t off = row * 128 + ((c ^ (row & 7)) << 4);
            *(uint4*)(sm8 + SM_A + off) = w;
        }
    }
    __syncthreads();

    // ---- layer 2: C[128,64] = Ah @ W2h ----
    float acc2[2][8][4];
    #pragma unroll
    for (int mt = 0; mt < 2; mt++)
        #pragma unroll
        for (int nt = 0; nt < 8; nt++)
            #pragma unroll
            for (int e = 0; e < 4; e++) acc2[mt][nt][e] = 0.0f;

    #pragma unroll
    for (int kt = 0; kt < 4; kt++) {
        uint32_t ah[2][4];
        #pragma unroll
        for (int mt = 0; mt < 2; mt++) {
            int r = rbase + mt * 16 + (lane & 15);
            uint32_t cb = kt * 32 + ((lane >> 4) << 4);
            uint32_t off = r * 128 + (cb ^ ((r & 7) << 4));
            ldmatrix4(ah[mt][0], ah[mt][1], ah[mt][2], ah[mt][3], smb + SM_A + off);
        }
        #pragma unroll
        for (int nt = 0; nt < 8; nt++) {
            uint2 b = w2f[(kt * 8 + nt) * 32 + lane];
            #pragma unroll
            for (int mt = 0; mt < 2; mt++) {
                float* d = acc2[mt][nt];
                mma16816(d[0], d[1], d[2], d[3], ah[mt][0], ah[mt][1], ah[mt][2], ah[mt][3], b.x, b.y);
            }
        }
    }

    // ---- register epilogue L2 + fragment pack: h2 = relu(C+b2) -> A fragments ----
    uint32_t a3f[2][4][4];   // [mt][kt][reg]
    #pragma unroll
    for (int mt = 0; mt < 2; mt++) {
        #pragma unroll
        for (int nt = 0; nt < 8; nt++) {
            int cn = nt * 8 + 2 * q;
            float2 bb = *(const float2*)&smallf[64 + cn];
            float v0 = fmaxf(acc2[mt][nt][0] + bb.x, 0.0f);
            float v1 = fmaxf(acc2[mt][nt][1] + bb.y, 0.0f);
            float v2 = fmaxf(acc2[mt][nt][2] + bb.x, 0.0f);
            float v3 = fmaxf(acc2[mt][nt][3] + bb.y, 0.0f);
            int kt = nt >> 1;
            int h  = (nt & 1) << 1;
            a3f[mt][kt][h + 0] = packh2(v0, v1);
            a3f[mt][kt][h + 1] = packh2(v2, v3);
        }
    }

    // ---- layer 3: C[128,32] = Ah @ W3h (A from registers) ----
    float acc3[2][4][4];
    #pragma unroll
    for (int mt = 0; mt < 2; mt++)
        #pragma unroll
        for (int nt = 0; nt < 4; nt++)
            #pragma unroll
            for (int e = 0; e < 4; e++) acc3[mt][nt][e] = 0.0f;

    #pragma unroll
    for (int kt = 0; kt < 4; kt++) {
        #pragma unroll
        for (int nt = 0; nt < 4; nt++) {
            uint2 b = w3f[(kt * 4 + nt) * 32 + lane];
            #pragma unroll
            for (int mt = 0; mt < 2; mt++) {
                float* d = acc3[mt][nt];
                mma16816(d[0], d[1], d[2], d[3],
                         a3f[mt][kt][0], a3f[mt][kt][1], a3f[mt][kt][2], a3f[mt][kt][3],
                         b.x, b.y);
            }
        }
    }

    // ---- epilogue L3: relu(C + b3) . W4, quad reduce, write (float2 pairs) ----
    #pragma unroll
    for (int mt = 0; mt < 2; mt++) {
        float sa = 0.0f, sb = 0.0f;
        #pragma unroll
        for (int nt = 0; nt < 4; nt++) {
            int cn = nt * 8 + 2 * q;
            float2 b3p = *(const float2*)&smallf[128 + cn];
            float2 w4p = *(const float2*)&smallf[160 + cn];
            sa = fmaf(fmaxf(acc3[mt][nt][0] + b3p.x, 0.0f), w4p.x, sa);
            sa = fmaf(fmaxf(acc3[mt][nt][1] + b3p.y, 0.0f), w4p.y, sa);
            sb = fmaf(fmaxf(acc3[mt][nt][2] + b3p.x, 0.0f), w4p.x, sb);
            sb = fmaf(fmaxf(acc3[mt][nt][3] + b3p.y, 0.0f), w4p.y, sb);
        }
        sa += __shfl_xor_sync(0xFFFFFFFFu, sa, 1);
        sa += __shfl_xor_sync(0xFFFFFFFFu, sa, 2);
        sb += __shfl_xor_sync(0xFFFFFFFFu, sb, 1);
        sb += __shfl_xor_sync(0xFFFFFFFFu, sb, 2);
        if (q == 0) {
            int ra = blockIdx.x * 128 + rbase + mt * 16 + qr;
            float b4v = smallf[192];
            if (ra < T)     out[ra]     = sa + b4v;
            if (ra + 8 < T) out[ra + 8] = sb + b4v;
        }
    }
}

// ================= launcher (fork-join: base1 overlaps the scan chain) =============
extern "C" void kernel_launch(void* const* d_in, const int* in_sizes, int n_in,
                              void* d_out, int out_size) {
    const float* x          = (const float*)d_in[0];
    const float* h_dag      = (const float*)d_in[1];
    const float* h_glob     = (const float*)d_in[2];
    const int* ptr          = (const int*)d_in[3];
    const int* job_idx      = (const int*)d_in[4];
    const int* num_exec     = (const int*)d_in[5];
    const int* exec_aidx    = (const int*)d_in[6];
    const float* W1 = (const float*)d_in[7];
    const float* b1 = (const float*)d_in[8];
    const float* W2 = (const float*)d_in[9];
    const float* b2 = (const float*)d_in[10];
    const float* W3 = (const float*)d_in[11];
    const float* b3 = (const float*)d_in[12];
    const float* W4 = (const float*)d_in[13];
    const float* b4 = (const float*)d_in[14];
    float* out = (float*)d_out;

    int J = in_sizes[4];
    int T = in_sizes[6];

    static cudaStream_t s1 = nullptr;
    static cudaEvent_t evF = nullptr, evJ = nullptr;
    if (s1 == nullptr) {
        cudaStreamCreateWithFlags(&s1, cudaStreamNonBlocking);
        cudaEventCreateWithFlags(&evF, cudaEventDisableTiming);
        cudaEventCreateWithFlags(&evJ, cudaEventDisableTiming);
        cudaFuncSetAttribute(k_mlp_mma, cudaFuncAttributeMaxDynamicSharedMemorySize, KM_SMEM);
    }

    int nblocks256 = (J + 255) / 256;

    // fork: base1 on side stream (depends only on inputs)
    cudaEventRecord(evF, 0);
    cudaStreamWaitEvent(s1, evF, 0);
    k_base1<<<(J + 63) / 64, 256, 0, s1>>>(x, h_dag, h_glob, ptr, job_idx, W1, b1, J);
    cudaEventRecord(evJ, s1);

    // main stream: scan chain + weight prep
    k_p1<<<nblocks256 + 7, 256>>>(job_idx, num_exec, J, W1, W2, b2, W3, b3, W4, b4);
    k_p3<<<nblocks256, 256>>>(J);

    // join, then main MLP
    cudaStreamWaitEvent(0, evJ, 0);
    k_mlp_mma<<<(T + 127) / 128, 128, KM_SMEM>>>(exec_aidx, out, T);
}

// round 16
// speedup vs baseline: 1.1209x; 1.0453x over previous
#include <cuda_runtime.h>
#include <cuda_fp16.h>
#include <stdint.h>

// ---------------- problem constants ----------------
#define NUM_EXEC   50
#define MAXB       60000
#define MAXT       (MAXB * NUM_EXEC)

typedef unsigned long long ull;

// ---------------- device scratch ----------------
__device__ int   g_nsel[MAXB];
__device__ int   g_blocksum[512];
__device__ int   g_rowjob[MAXT];
__device__ float g_base1[(size_t)MAXB * 64];
// prepped weight blob (exact smem image), FRAGMENT-ORDERED B, pure fp16:
//  [0,8192)      W2 frags: kt(4) x nt(8) x lane(32): uint2 {b0,b1}
//  [8192,12288)  W3 frags: kt(4) x nt(4) x lane(32): uint2
//  [12288,13312) fp32 smalls: W1L[64] b2[64] b3[32] W4[32] b4[1]
__device__ __align__(16) unsigned char g_wblob[13312];

// ---------------- helpers ----------------
__device__ __forceinline__ ull fma2(ull a, ull b, ull c) {
    ull d;
    asm("fma.rn.f32x2 %0, %1, %2, %3;" : "=l"(d) : "l"(a), "l"(b), "l"(c));
    return d;
}
__device__ __forceinline__ ull pack2(float a, float b) {
    ull r;
    asm("mov.b64 %0, {%1,%2};" : "=l"(r) : "f"(a), "f"(b));
    return r;
}
__device__ __forceinline__ void unpack2(ull v, float& a, float& b) {
    asm("mov.b64 {%0,%1}, %2;" : "=f"(a), "=f"(b) : "l"(v));
}
// pack (lo_elem, hi_elem) -> f16x2, lo_elem in low 16 bits
__device__ __forceinline__ uint32_t packh2(float lov, float hiv) {
    uint32_t r;
    asm("cvt.rn.f16x2.f32 %0, %1, %2;" : "=r"(r) : "f"(hiv), "f"(lov));
    return r;
}
__device__ __forceinline__ void mma16816(float& d0, float& d1, float& d2, float& d3,
                                         uint32_t a0, uint32_t a1, uint32_t a2, uint32_t a3,
                                         uint32_t b0, uint32_t b1) {
    asm volatile("mma.sync.aligned.m16n8k16.row.col.f32.f16.f16.f32 "
                 "{%0,%1,%2,%3}, {%4,%5,%6,%7}, {%8,%9}, {%0,%1,%2,%3};"
                 : "+f"(d0), "+f"(d1), "+f"(d2), "+f"(d3)
                 : "r"(a0), "r"(a1), "r"(a2), "r"(a3), "r"(b0), "r"(b1));
}

// ================= prologue 1: nsel gather + block sums, FUSED with weight prep ======
__global__ void k_p1(const int* __restrict__ job_indices,
                     const int* __restrict__ num_exec_acts, int J,
                     const float* __restrict__ W1, const float* __restrict__ W2,
                     const float* __restrict__ b2, const float* __restrict__ W3,
                     const float* __restrict__ b3, const float* __restrict__ W4,
                     const float* __restrict__ b4) {
    int nb = (J + 255) >> 8;
    if ((int)blockIdx.x < nb) {
        __shared__ int s[256];
        int j = blockIdx.x * 256 + threadIdx.x;
        int v = 0;
        if (j < J) { v = num_exec_acts[job_indices[j]]; g_nsel[j] = v; }
        s[threadIdx.x] = v;
        __syncthreads();
        #pragma unroll
        for (int o = 128; o > 0; o >>= 1) {
            if (threadIdx.x < o) s[threadIdx.x] += s[threadIdx.x + o];
            __syncthreads();
        }
        if (threadIdx.x == 0) g_blocksum[blockIdx.x] = s[0];
    } else {
        int tid = (blockIdx.x - nb) * 256 + threadIdx.x;
        if (tid < 1024) {                 // W2 fragments: kt(4) x nt(8) x lane(32)
            int kt = tid >> 8, nt = (tid >> 5) & 7, lane = tid & 31;
            int q = lane & 3, qr = lane >> 2;
            int n = nt * 8 + qr;
            int k0 = kt * 16 + 2 * q;
            uint2 v;
            v.x = packh2(W2[(k0    ) * 64 + n], W2[(k0 + 1) * 64 + n]);
            v.y = packh2(W2[(k0 + 8) * 64 + n], W2[(k0 + 9) * 64 + n]);
            ((uint2*)g_wblob)[tid] = v;
        } else if (tid < 1536) {          // W3 fragments: kt(4) x nt(4) x lane(32)
            int e = tid - 1024;
            int kt = e >> 7, nt = (e >> 5) & 3, lane = e & 31;
            int q = lane & 3, qr = lane >> 2;
            int n = nt * 8 + qr;
            int k0 = kt * 16 + 2 * q;
            uint2 v;
            v.x = packh2(W3[(k0    ) * 32 + n], W3[(k0 + 1) * 32 + n]);
            v.y = packh2(W3[(k0 + 8) * 32 + n], W3[(k0 + 9) * 32 + n]);
            ((uint2*)g_wblob)[1024 + e] = v;
        } else if (tid < 1536 + 256) {
            int i = tid - 1536;
            float* s = (float*)(g_wblob + 12288);
            if (i < 64)       s[i] = W1[35 * 64 + i];
            else if (i < 128) s[i] = b2[i - 64];
            else if (i < 160) s[i] = b3[i - 128];
            else if (i < 192) s[i] = W4[i - 160];
            else if (i == 192) s[192] = b4[0];
        }
    }
}

// ================= prologue 2: per-job start + row->job fill, scan FUSED in ==========
__global__ void k_p3(int J) {
    __shared__ int s[256];
    __shared__ int bs[256];
    int tid = threadIdx.x;
    int nb = (J + 255) >> 8;
    bs[tid] = (tid < nb) ? g_blocksum[tid] : 0;
    int j = blockIdx.x * 256 + tid;
    int v = (j < J) ? g_nsel[j] : 0;
    s[tid] = v;
    __syncthreads();
    for (int o = 1; o < 256; o <<= 1) {
        int tb = (tid >= o) ? bs[tid - o] : 0;
        int ts = (tid >= o) ? s[tid - o]  : 0;
        __syncthreads();
        bs[tid] += tb;
        s[tid]  += ts;
        __syncthreads();
    }
    if (j < J) {
        int blockpre = (blockIdx.x == 0) ? 0 : bs[blockIdx.x - 1];
        int start = (s[tid] - v) + blockpre;
        for (int k = 0; k < v; k++) g_rowjob[start + k] = j;
    }
}

// ================= base1: smem W1, 64 jobs/block, 4 jobs in flight x 2 chains ========
__global__ void __launch_bounds__(256) k_base1(
    const float* __restrict__ x, const float* __restrict__ h_dag,
    const float* __restrict__ h_glob,
    const int* __restrict__ ptr, const int* __restrict__ jidx,
    const float* __restrict__ W1, const float* __restrict__ b1, int J) {
    __shared__ __align__(16) float sW1[35 * 64];
    __shared__ __align__(16) float sB1[64];
    for (int i = threadIdx.x; i < 35 * 64; i += blockDim.x) sW1[i] = W1[i];
    for (int i = threadIdx.x; i < 64; i += blockDim.x)      sB1[i] = b1[i];
    __syncthreads();

    const int warp = threadIdx.x >> 5;
    const int lane = threadIdx.x & 31;
    const int jbase = blockIdx.x * 64 + warp;

    #pragma unroll 1
    for (int it = 0; it < 2; it++) {
        int jm = jbase + it * 32;
        if (jm >= J) break;

        bool hv[4];
        const float *xr[4], *hd[4], *hg[4];
        #pragma unroll
        for (int c = 0; c < 4; c++) {
            int j = jm + c * 8;
            hv[c] = (j < J);
            int jc = hv[c] ? j : jm;
            int ji = jidx[jc];
            xr[c] = x + (long long)ptr[ji] * 5;
            hd[c] = h_dag + (long long)ji * 16;
            hg[c] = h_glob + (long long)jc * 16;
        }

        ull bias = pack2(sB1[2 * lane], sB1[2 * lane + 1]);
        ull zero = pack2(0.0f, 0.0f);
        ull aA[4], aB[4];
        #pragma unroll
        for (int c = 0; c < 4; c++) { aA[c] = bias; aB[c] = zero; }

        #pragma unroll
        for (int i = 0; i < 3; i++) {
            ull w = *(const ull*)&sW1[i * 64 + 2 * lane];
            #pragma unroll
            for (int c = 0; c < 4; c++) {
                float v = xr[c][i];
                aA[c] = fma2(pack2(v, v), w, aA[c]);
            }
        }
        #pragma unroll
        for (int i = 0; i < 16; i++) {
            ull w = *(const ull*)&sW1[(3 + i) * 64 + 2 * lane];
            #pragma unroll
            for (int c = 0; c < 4; c++) {
                float v = hd[c][i];
                if (i & 1) aB[c] = fma2(pack2(v, v), w, aB[c]);
                else       aA[c] = fma2(pack2(v, v), w, aA[c]);
            }
        }
        #pragma unroll
        for (int i = 0; i < 16; i++) {
            ull w = *(const ull*)&sW1[(19 + i) * 64 + 2 * lane];
            #pragma unroll
            for (int c = 0; c < 4; c++) {
                float v = hg[c][i];
                if (i & 1) aB[c] = fma2(pack2(v, v), w, aB[c]);
                else       aA[c] = fma2(pack2(v, v), w, aA[c]);
            }
        }

        #pragma unroll
        for (int c = 0; c < 4; c++) {
            if (!hv[c]) continue;
            float xa, xb, ya, yb;
            unpack2(aA[c], xa, xb);
            unpack2(aB[c], ya, yb);
            float* d = g_base1 + (size_t)(jm + c * 8) * 64 + 2 * lane;
            d[0] = xa + ya;
            d[1] = xb + yb;
        }
    }
}

// ================= main: fully register-resident MLP (no A smem), 128 rows/CTA =====
// dyn smem: [0,13312) weight blob image only
#define KM_SMEM 13312

__global__ void __launch_bounds__(128, 5) k_mlp_mma(
    const int* __restrict__ exec_act_idx, float* __restrict__ out, int T) {

    extern __shared__ unsigned char sm8[];
    const float* smallf = (const float*)(sm8 + 12288);
    const uint2* w2f = (const uint2*)sm8;                       // [kt*8+nt][lane]
    const uint2* w3f = (const uint2*)(sm8 + 8192);              // [kt*4+nt][lane]

    const int tid  = threadIdx.x;
    const int warp = tid >> 5;
    const int lane = tid & 31;
    const int q    = lane & 3;
    const int qr   = lane >> 2;
    const int rbase = warp * 32;

    // ---- copy prepped weights + smalls (13312 B = 832 uint4) ----
    {
        const uint4* src = (const uint4*)g_wblob;
        uint4* dst = (uint4*)sm8;
        #pragma unroll
        for (int it = 0; it < 7; it++) {
            int i = tid + it * 128;
            if (i < 832) dst[i] = src[i];
        }
    }
    __syncthreads();

    const int t0 = blockIdx.x * 128;

    // ---- per-thread fragment rows: rbase + {qr, qr+8, 16+qr, 24+qr} ----
    const float* bp[4];
    float kfr[4];
    #pragma unroll
    for (int c = 0; c < 4; c++) {
        int r  = rbase + ((c & 1) << 3) + ((c >> 1) << 4) + qr;
        int tg = t0 + r;
        int tc = (tg < T) ? tg : (T - 1);
        int j  = g_rowjob[tc];
        bp[c]  = g_base1 + (size_t)j * 64;
        kfr[c] = (float)exec_act_idx[tc] * (1.0f / (float)NUM_EXEC);
    }

    // ---- layer 2: C[128,64] = Ah @ W2h, A fragments computed in registers ----
    float acc2[2][8][4];
    #pragma unroll
    for (int mt = 0; mt < 2; mt++)
        #pragma unroll
        for (int nt = 0; nt < 8; nt++)
            #pragma unroll
            for (int e = 0; e < 4; e++) acc2[mt][nt][e] = 0.0f;

    #pragma unroll
    for (int kt = 0; kt < 4; kt++) {
        // W1L pairs for this thread's k positions
        float2 wu = *(const float2*)&smallf[kt * 16 + 2 * q];
        float2 wv = *(const float2*)&smallf[kt * 16 + 8 + 2 * q];
        // build A fragments: af[mt] = {a0,a1,a2,a3}
        uint32_t af[2][4];
        #pragma unroll
        for (int c = 0; c < 4; c++) {
            const float* rp = bp[c] + kt * 16 + 2 * q;
            float2 u = *(const float2*)rp;
            float2 v = *(const float2*)(rp + 8);
            float kf = kfr[c];
            float h0 = fmaxf(fmaf(kf, wu.x, u.x), 0.0f);
            float h1 = fmaxf(fmaf(kf, wu.y, u.y), 0.0f);
            float h2 = fmaxf(fmaf(kf, wv.x, v.x), 0.0f);
            float h3 = fmaxf(fmaf(kf, wv.y, v.y), 0.0f);
            int mt = c >> 1;
            int rr = c & 1;
            af[mt][rr]     = packh2(h0, h1);   // a0 (row qr) / a1 (row qr+8)
            af[mt][rr + 2] = packh2(h2, h3);   // a2 / a3
        }
        #pragma unroll
        for (int nt = 0; nt < 8; nt++) {
            uint2 b = w2f[(kt * 8 + nt) * 32 + lane];
            #pragma unroll
            for (int mt = 0; mt < 2; mt++) {
                float* d = acc2[mt][nt];
                mma16816(d[0], d[1], d[2], d[3], af[mt][0], af[mt][1], af[mt][2], af[mt][3], b.x, b.y);
            }
        }
    }

    // ---- register epilogue L2 + fragment pack: h2 = relu(C+b2) -> A fragments ----
    uint32_t a3f[2][4][4];   // [mt][kt][reg]
    #pragma unroll
    for (int mt = 0; mt < 2; mt++) {
        #pragma unroll
        for (int nt = 0; nt < 8; nt++) {
            int cn = nt * 8 + 2 * q;
            float2 bb = *(const float2*)&smallf[64 + cn];
            float v0 = fmaxf(acc2[mt][nt][0] + bb.x, 0.0f);
            float v1 = fmaxf(acc2[mt][nt][1] + bb.y, 0.0f);
            float v2 = fmaxf(acc2[mt][nt][2] + bb.x, 0.0f);
            float v3 = fmaxf(acc2[mt][nt][3] + bb.y, 0.0f);
            int kt = nt >> 1;
            int h  = (nt & 1) << 1;
            a3f[mt][kt][h + 0] = packh2(v0, v1);
            a3f[mt][kt][h + 1] = packh2(v2, v3);
        }
    }

    // ---- layer 3: C[128,32] = Ah @ W3h (A from registers) ----
    float acc3[2][4][4];
    #pragma unroll
    for (int mt = 0; mt < 2; mt++)
        #pragma unroll
        for (int nt = 0; nt < 4; nt++)
            #pragma unroll
            for (int e = 0; e < 4; e++) acc3[mt][nt][e] = 0.0f;

    #pragma unroll
    for (int kt = 0; kt < 4; kt++) {
        #pragma unroll
        for (int nt = 0; nt < 4; nt++) {
            uint2 b = w3f[(kt * 4 + nt) * 32 + lane];
            #pragma unroll
            for (int mt = 0; mt < 2; mt++) {
                float* d = acc3[mt][nt];
                mma16816(d[0], d[1], d[2], d[3],
                         a3f[mt][kt][0], a3f[mt][kt][1], a3f[mt][kt][2], a3f[mt][kt][3],
                         b.x, b.y);
            }
        }
    }

    // ---- epilogue L3: relu(C + b3) . W4, quad reduce, write (float2 pairs) ----
    #pragma unroll
    for (int mt = 0; mt < 2; mt++) {
        float sa = 0.0f, sb = 0.0f;
        #pragma unroll
        for (int nt = 0; nt < 4; nt++) {
            int cn = nt * 8 + 2 * q;
            float2 b3p = *(const float2*)&smallf[128 + cn];
            float2 w4p = *(const float2*)&smallf[160 + cn];
            sa = fmaf(fmaxf(acc3[mt][nt][0] + b3p.x, 0.0f), w4p.x, sa);
            sa = fmaf(fmaxf(acc3[mt][nt][1] + b3p.y, 0.0f), w4p.y, sa);
            sb = fmaf(fmaxf(acc3[mt][nt][2] + b3p.x, 0.0f), w4p.x, sb);
            sb = fmaf(fmaxf(acc3[mt][nt][3] + b3p.y, 0.0f), w4p.y, sb);
        }
        sa += __shfl_xor_sync(0xFFFFFFFFu, sa, 1);
        sa += __shfl_xor_sync(0xFFFFFFFFu, sa, 2);
        sb += __shfl_xor_sync(0xFFFFFFFFu, sb, 1);
        sb += __shfl_xor_sync(0xFFFFFFFFu, sb, 2);
        if (q == 0) {
            int ra = t0 + rbase + mt * 16 + qr;
            float b4v = smallf[192];
            if (ra < T)     out[ra]     = sa + b4v;
            if (ra + 8 < T) out[ra + 8] = sb + b4v;
        }
    }
}

// ================= launcher (fork-join: base1 overlaps the scan chain) =============
extern "C" void kernel_launch(void* const* d_in, const int* in_sizes, int n_in,
                              void* d_out, int out_size) {
    const float* x          = (const float*)d_in[0];
    const float* h_dag      = (const float*)d_in[1];
    const float* h_glob     = (const float*)d_in[2];
    const int* ptr          = (const int*)d_in[3];
    const int* job_idx      = (const int*)d_in[4];
    const int* num_exec     = (const int*)d_in[5];
    const int* exec_aidx    = (const int*)d_in[6];
    const float* W1 = (const float*)d_in[7];
    const float* b1 = (const float*)d_in[8];
    const float* W2 = (const float*)d_in[9];
    const float* b2 = (const float*)d_in[10];
    const float* W3 = (const float*)d_in[11];
    const float* b3 = (const float*)d_in[12];
    const float* W4 = (const float*)d_in[13];
    const float* b4 = (const float*)d_in[14];
    float* out = (float*)d_out;

    int J = in_sizes[4];
    int T = in_sizes[6];

    static cudaStream_t s1 = nullptr;
    static cudaEvent_t evF = nullptr, evJ = nullptr;
    if (s1 == nullptr) {
        cudaStreamCreateWithFlags(&s1, cudaStreamNonBlocking);
        cudaEventCreateWithFlags(&evF, cudaEventDisableTiming);
        cudaEventCreateWithFlags(&evJ, cudaEventDisableTiming);
        cudaFuncSetAttribute(k_mlp_mma, cudaFuncAttributeMaxDynamicSharedMemorySize, KM_SMEM);
    }

    int nblocks256 = (J + 255) / 256;

    // fork: base1 on side stream (depends only on inputs)
    cudaEventRecord(evF, 0);
    cudaStreamWaitEvent(s1, evF, 0);
    k_base1<<<(J + 63) / 64, 256, 0, s1>>>(x, h_dag, h_glob, ptr, job_idx, W1, b1, J);
    cudaEventRecord(evJ, s1);

    // main stream: scan chain + weight prep
    k_p1<<<nblocks256 + 7, 256>>>(job_idx, num_exec, J, W1, W2, b2, W3, b3, W4, b4);
    k_p3<<<nblocks256, 256>>>(J);

    // join, then main MLP
    cudaStreamWaitEvent(0, evJ, 0);
    k_mlp_mma<<<(T + 127) / 128, 128, KM_SMEM>>>(exec_aidx, out, T);
}